// round 3
// baseline (speedup 1.0000x reference)
#include <cuda_runtime.h>
#include <cuda_bf16.h>
#include <cstdint>

// ---------------- Problem constants ----------------
#define CB   4
#define CL   512
#define CD   1024
#define CED  2048
#define CNS  16
#define CRK  64
#define CKC  4
#define CML  (CB*CL)        // 2048
#define BLED (CB*CL*CED)    // 4194304

// ---------------- Scratch ----------------
__device__ float g_xz[CB*CL*2*CED];
__device__ float g_xc[2*BLED];
__device__ float g_dbc[2*CML*96];
__device__ float g_delta[2*BLED];
__device__ float g_y[2*BLED];
__device__ float g_yc[BLED];

// ---------------- helpers ----------------
__device__ __forceinline__ float softplusf(float x) {
    return fmaxf(x, 0.f) + log1pf(__expf(-fabsf(x)));
}
__device__ __forceinline__ float siluf(float x) {
    return x / (1.f + __expf(-x));
}
__device__ __forceinline__ float tf32r(float x) {
    uint32_t r; asm("cvt.rna.tf32.f32 %0, %1;" : "=r"(r) : "f"(x));
    return __uint_as_float(r);
}
__device__ __forceinline__ uint32_t tf32u(uint32_t x) {
    uint32_t r; asm("cvt.rna.tf32.f32 %0, %1;" : "=r"(r) : "f"(__uint_as_float(x)));
    return r;
}
__device__ __forceinline__ float ex2f(float x) {
    float y; asm("ex2.approx.ftz.f32 %0, %1;" : "=f"(y) : "f"(x));
    return y;
}
__device__ __forceinline__ void cp16(uint32_t dst, const void* src) {
    asm volatile("cp.async.cg.shared.global [%0], [%1], 16;" :: "r"(dst), "l"(src));
}
__device__ __forceinline__ void ldsm4(uint32_t& r0, uint32_t& r1, uint32_t& r2, uint32_t& r3, uint32_t addr) {
    asm volatile("ldmatrix.sync.aligned.m8n8.x4.shared.b16 {%0,%1,%2,%3}, [%4];"
                 : "=r"(r0), "=r"(r1), "=r"(r2), "=r"(r3) : "r"(addr));
}

__global__ void zero_k(float4* __restrict__ p, int n4) {
    int i = blockIdx.x * blockDim.x + threadIdx.x;
    if (i < n4) p[i] = make_float4(0.f, 0.f, 0.f, 0.f);
}

// ---------------- TF32 tensor-core NT GEMM ----------------
// C[M,N] = A[M,K] * B[N,K]^T.  BM=128, BK=32, 3-stage cp.async, ldmatrix frags,
// cvt.rna.tf32 fused on fragments (operands may be raw fp32).
// EPI: 0 none, 1 softplus(acc + bias[n]).
// DIRAX: 0 none; 1 dir=blockIdx.x (col0=0), split-K on z; 2 dir=blockIdx.z (no split-K).
template<int BN, int EPI, int DIRAX>
__global__ void __launch_bounds__(2*(BN/32)*32)
gemm_tf32(const float* __restrict__ A, int lda, size_t aStride,
          const float* __restrict__ B0, const float* __restrict__ B1, int ldb,
          float* __restrict__ C, int ldc, size_t cStride,
          int K, const float* __restrict__ bias0, const float* __restrict__ bias1)
{
    constexpr int BM = 128;
    constexpr int WARPS_N = BN/32;
    constexpr int THREADS = 2*WARPS_N*32;
    constexpr int LDK = 36;
    constexpr int STAGE = (BM+BN)*LDK;
    extern __shared__ float sm[];

    const int tid  = threadIdx.x;
    const int warp = tid >> 5, lane = tid & 31;
    const int wm = warp / WARPS_N, wn = warp % WARPS_N;
    const int g = lane >> 2, t = lane & 3;

    const int dir = (DIRAX==1) ? blockIdx.x : (DIRAX==2 ? blockIdx.z : 0);
    const int row0 = blockIdx.y * BM;
    const int col0 = (DIRAX==1) ? 0 : blockIdx.x * BN;
    const int nsplit = (DIRAX==2) ? 1 : gridDim.z;
    const int Kc = K / nsplit;
    const int kbase = (DIRAX==2) ? 0 : blockIdx.z * Kc;
    const int KT = Kc / 32;

    const float* Aeff = A + (size_t)dir * aStride;
    const float* Beff = dir ? B1 : B0;
    float*       Ceff = C + (size_t)dir * cStride;
    const float* bias = dir ? bias1 : bias0;

    float acc[4][4][4];
#pragma unroll
    for (int i = 0; i < 4; i++)
#pragma unroll
        for (int j = 0; j < 4; j++)
#pragma unroll
            for (int q = 0; q < 4; q++) acc[i][j][q] = 0.f;

    const uint32_t smem0 = (uint32_t)__cvta_generic_to_shared(sm);

    // per-lane ldmatrix base offsets (bytes, relative to stage base)
    const uint32_t aOff = (((lane & 7) + ((lane >> 3) & 1) * 8 + wm * 64) * LDK
                           + (lane >> 4) * 4) * 4u;
    const uint32_t bOff = (BM * LDK + ((lane & 7) + (lane >> 4) * 8 + wn * 32) * LDK
                           + ((lane >> 3) & 1) * 4) * 4u;

    auto load_tile = [&](int kt, int s) {
        float* As = sm + s*STAGE;
        float* Bs = As + BM*LDK;
        int k0 = kbase + kt*32;
#pragma unroll 2
        for (int i = tid; i < BM*8; i += THREADS) {
            int m = i >> 3, kq = (i & 7) << 2;
            cp16((uint32_t)__cvta_generic_to_shared(As + m*LDK + kq),
                 Aeff + (size_t)(row0+m)*lda + k0 + kq);
        }
#pragma unroll 2
        for (int i = tid; i < BN*8; i += THREADS) {
            int n = i >> 3, kq = (i & 7) << 2;
            cp16((uint32_t)__cvta_generic_to_shared(Bs + n*LDK + kq),
                 Beff + (size_t)(col0+n)*ldb + k0 + kq);
        }
    };

    auto comp = [&](int s) {
        const uint32_t base = smem0 + (uint32_t)(s*STAGE)*4u;
#pragma unroll
        for (int ks = 0; ks < 4; ks++) {
            const uint32_t kb = (uint32_t)(ks*8)*4u;
            uint32_t a[4][4], b[2][4];
#pragma unroll
            for (int mt = 0; mt < 4; mt++)
                ldsm4(a[mt][0], a[mt][1], a[mt][2], a[mt][3],
                      base + aOff + (uint32_t)(mt*16*LDK)*4u + kb);
#pragma unroll
            for (int np = 0; np < 2; np++)
                ldsm4(b[np][0], b[np][1], b[np][2], b[np][3],
                      base + bOff + (uint32_t)(np*16*LDK)*4u + kb);
#pragma unroll
            for (int mt = 0; mt < 4; mt++)
#pragma unroll
                for (int q = 0; q < 4; q++) a[mt][q] = tf32u(a[mt][q]);
#pragma unroll
            for (int np = 0; np < 2; np++)
#pragma unroll
                for (int q = 0; q < 4; q++) b[np][q] = tf32u(b[np][q]);
#pragma unroll
            for (int mt = 0; mt < 4; mt++)
#pragma unroll
                for (int nt = 0; nt < 4; nt++) {
                    const uint32_t bb0 = b[nt>>1][(nt&1)*2 + 0];
                    const uint32_t bb1 = b[nt>>1][(nt&1)*2 + 1];
                    asm volatile(
                        "mma.sync.aligned.m16n8k8.row.col.f32.tf32.tf32.f32 "
                        "{%0,%1,%2,%3}, {%4,%5,%6,%7}, {%8,%9}, {%0,%1,%2,%3};"
                        : "+f"(acc[mt][nt][0]), "+f"(acc[mt][nt][1]),
                          "+f"(acc[mt][nt][2]), "+f"(acc[mt][nt][3])
                        : "r"(a[mt][0]), "r"(a[mt][1]), "r"(a[mt][2]), "r"(a[mt][3]),
                          "r"(bb0), "r"(bb1));
                }
        }
    };

    load_tile(0, 0);
    asm volatile("cp.async.commit_group;");
    if (KT > 1) load_tile(1, 1);
    asm volatile("cp.async.commit_group;");

    for (int kt = 0; kt < KT; kt++) {
        asm volatile("cp.async.wait_group 1;");
        __syncthreads();
        if (kt + 2 < KT) load_tile(kt + 2, (kt + 2) % 3);
        asm volatile("cp.async.commit_group;");
        comp(kt % 3);
    }

    const bool use_atomic = (DIRAX != 2 && nsplit > 1);
#pragma unroll
    for (int mt = 0; mt < 4; mt++) {
        int row = row0 + wm*64 + mt*16 + g;
#pragma unroll
        for (int nt = 0; nt < 4; nt++) {
            int col = col0 + wn*32 + nt*8 + 2*t;
            float v0 = acc[mt][nt][0], v1 = acc[mt][nt][1];
            float v2 = acc[mt][nt][2], v3 = acc[mt][nt][3];
            if (EPI == 1) {
                v0 = softplusf(v0 + bias[col]);
                v1 = softplusf(v1 + bias[col+1]);
                v2 = softplusf(v2 + bias[col]);
                v3 = softplusf(v3 + bias[col+1]);
            }
            if (use_atomic) {
                atomicAdd(&Ceff[(size_t)row*ldc + col],       v0);
                atomicAdd(&Ceff[(size_t)row*ldc + col + 1],   v1);
                atomicAdd(&Ceff[(size_t)(row+8)*ldc + col],   v2);
                atomicAdd(&Ceff[(size_t)(row+8)*ldc + col+1], v3);
            } else {
                *(float2*)&Ceff[(size_t)row*ldc + col]     = make_float2(v0, v1);
                *(float2*)&Ceff[(size_t)(row+8)*ldc + col] = make_float2(v2, v3);
            }
        }
    }
}

// ---------------- causal depthwise conv + SiLU (both dirs) ----------------
__global__ void conv_silu_kernel(const float* __restrict__ xz,
                                 const float* __restrict__ cw0, const float* __restrict__ cb0,
                                 const float* __restrict__ cw1, const float* __restrict__ cb1,
                                 float* __restrict__ xc)
{
    int idx = blockIdx.x * blockDim.x + threadIdx.x;
    int e   = idx & (CED-1);
    int t   = (idx >> 11) & (CL-1);
    int b   = (idx >> 20) & (CB-1);
    int dir = idx >> 22;

    const float* w = dir ? cw1 : cw0;
    float acc = (dir ? cb1 : cb0)[e];
#pragma unroll
    for (int j = 0; j < CKC; j++) {
        int ts = t - (CKC-1) + j;
        if (ts >= 0) {
            int tg = dir ? (CL-1-ts) : ts;
            acc = fmaf(w[e*CKC + j], xz[((size_t)(b*CL + tg) << 12) + e], acc);
        }
    }
    xc[idx] = tf32r(siluf(acc));
}

// ---------------- selective scan, both dirs in one launch -----------------
#define SCAN_TC 16
__global__ void __launch_bounds__(128)
scan_kernel(const float* __restrict__ delta,
            const float* __restrict__ xc,
            const float* __restrict__ dbc,
            const float* __restrict__ xz,
            const float* __restrict__ A_log_f, const float* __restrict__ A_log_b,
            const float* __restrict__ Dp_f,    const float* __restrict__ Dp_b,
            float* __restrict__ y)
{
    __shared__ float sD[SCAN_TC][128];
    __shared__ float sX[SCAN_TC][128];
    __shared__ float sZ[SCAN_TC][128];
    __shared__ float sB[SCAN_TC][CNS];
    __shared__ float sC[SCAN_TC][CNS];

    const int e   = blockIdx.x * 128 + threadIdx.x;
    const int b   = blockIdx.y;
    const int dir = blockIdx.z;
    const int tx  = threadIdx.x;

    const float* dlt = delta + (size_t)dir * BLED;
    const float* xcd = xc    + (size_t)dir * BLED;
    const float* dbd = dbc   + (size_t)dir * CML * 96;
    float*       yd  = y     + (size_t)dir * BLED;
    const float* A_log = dir ? A_log_b : A_log_f;
    const float* Dp    = dir ? Dp_b    : Dp_f;

    float Areg[CNS];
#pragma unroll
    for (int n = 0; n < CNS; n++)
        Areg[n] = -__expf(A_log[e*CNS + n]) * 1.4426950408889634f;
    const float Dpe = Dp[e];

    float h[CNS];
#pragma unroll
    for (int n = 0; n < CNS; n++) h[n] = 0.f;

    for (int t0 = 0; t0 < CL; t0 += SCAN_TC) {
        __syncthreads();
#pragma unroll
        for (int it = 0; it < SCAN_TC; it++) {
            int t = t0 + it;
            size_t r = (size_t)(b*CL + t) * CED + e;
            sD[it][tx] = dlt[r];
            sX[it][tx] = xcd[r];
            int tz = dir ? (CL-1-t) : t;
            sZ[it][tx] = xz[((size_t)(b*CL + tz) << 12) + CED + e];
        }
        for (int j = tx; j < SCAN_TC*CNS; j += 128) {
            int it = j >> 4, n = j & (CNS-1);
            size_t r = (size_t)(b*CL + t0 + it) * 96;
            sB[it][n] = dbd[r + CRK + n];
            sC[it][n] = dbd[r + CRK + CNS + n];
        }
        __syncthreads();

#pragma unroll
        for (int it = 0; it < SCAN_TC; it++) {
            float d  = sD[it][tx];
            float xv = sX[it][tx];
            float dx = d * xv;
            float y0 = 0.f, y1 = 0.f, y2 = 0.f, y3 = 0.f;
#pragma unroll
            for (int n = 0; n < CNS; n += 4) {
                float dA0 = ex2f(d * Areg[n+0]);
                float dA1 = ex2f(d * Areg[n+1]);
                float dA2 = ex2f(d * Areg[n+2]);
                float dA3 = ex2f(d * Areg[n+3]);
                h[n+0] = fmaf(dA0, h[n+0], dx * sB[it][n+0]);
                h[n+1] = fmaf(dA1, h[n+1], dx * sB[it][n+1]);
                h[n+2] = fmaf(dA2, h[n+2], dx * sB[it][n+2]);
                h[n+3] = fmaf(dA3, h[n+3], dx * sB[it][n+3]);
                y0 = fmaf(h[n+0], sC[it][n+0], y0);
                y1 = fmaf(h[n+1], sC[it][n+1], y1);
                y2 = fmaf(h[n+2], sC[it][n+2], y2);
                y3 = fmaf(h[n+3], sC[it][n+3], y3);
            }
            float zv = sZ[it][tx];
            float yo = ((y0+y1) + (y2+y3)) + Dpe * xv;
            yd[(size_t)(b*CL + t0 + it)*CED + e] = yo * siluf(zv);
        }
    }
}

// ---------------- combine (tf32-rounded output) ------------------
__global__ void combine_kernel(const float* __restrict__ y0,
                               const float* __restrict__ y1,
                               float* __restrict__ yc)
{
    int idx = blockIdx.x * blockDim.x + threadIdx.x;
    int e = idx & (CED-1);
    int t = (idx >> 11) & (CL-1);
    int b = idx >> 20;
    float a  = y0[idx];
    float bb = y1[(size_t)(b*CL + (CL-1-t))*CED + e];
    yc[idx] = tf32r(0.5f * (a + bb));
}

// ---------------- launch ----------------
extern "C" void kernel_launch(void* const* d_in, const int* in_sizes, int n_in,
                              void* d_out, int out_size)
{
    const float* x      = (const float*)d_in[0];
    const float* W_in   = (const float*)d_in[1];
    const float* conv_w = (const float*)d_in[2];
    const float* conv_b = (const float*)d_in[3];
    const float* Wx     = (const float*)d_in[4];
    const float* Wdt    = (const float*)d_in[5];
    const float* b_dt   = (const float*)d_in[6];
    const float* A_log  = (const float*)d_in[7];
    const float* Dp     = (const float*)d_in[8];
    const float* conv_w_b = (const float*)d_in[9];
    const float* conv_b_b = (const float*)d_in[10];
    const float* Wx_b   = (const float*)d_in[11];
    const float* Wdt_b  = (const float*)d_in[12];
    const float* b_dt_b = (const float*)d_in[13];
    const float* A_log_b= (const float*)d_in[14];
    const float* Dp_b   = (const float*)d_in[15];
    const float* W_out  = (const float*)d_in[16];
    float* out = (float*)d_out;

    float *p_xz, *p_xc, *p_dbc, *p_delta, *p_y, *p_yc;
    cudaGetSymbolAddress((void**)&p_xz,    g_xz);
    cudaGetSymbolAddress((void**)&p_xc,    g_xc);
    cudaGetSymbolAddress((void**)&p_dbc,   g_dbc);
    cudaGetSymbolAddress((void**)&p_delta, g_delta);
    cudaGetSymbolAddress((void**)&p_y,     g_y);
    cudaGetSymbolAddress((void**)&p_yc,    g_yc);

    constexpr int SMEM128 = (128+128)*36*4*3;   // 110592
    constexpr int SMEM96  = (128+96) *36*4*3;   //  96768
    constexpr int SMEM64  = (128+64) *36*4*3;   //  82944
    cudaFuncSetAttribute(gemm_tf32<128,0,0>, cudaFuncAttributeMaxDynamicSharedMemorySize, SMEM128);
    cudaFuncSetAttribute(gemm_tf32<128,1,2>, cudaFuncAttributeMaxDynamicSharedMemorySize, SMEM128);
    cudaFuncSetAttribute(gemm_tf32<96,0,1>,  cudaFuncAttributeMaxDynamicSharedMemorySize, SMEM96);
    cudaFuncSetAttribute(gemm_tf32<64,0,0>,  cudaFuncAttributeMaxDynamicSharedMemorySize, SMEM64);

    // 0) zero dbc accumulators (split-K atomics)
    zero_k<<<(2*CML*96/4 + 255)/256, 256>>>((float4*)p_dbc, 2*CML*96/4);

    // 1) xz = x @ W_in^T : [2048,1024] x [4096,1024]^T
    gemm_tf32<128,0,0><<<dim3(32,16,1), 256, SMEM128>>>(
        x, CD, 0, W_in, W_in, CD, p_xz, 2*CED, 0, CD, nullptr, nullptr);

    // 2) conv + silu (both dirs)
    conv_silu_kernel<<<(2*BLED)/256, 256>>>(p_xz, conv_w, conv_b, conv_w_b, conv_b_b, p_xc);

    // 3) dbc = xc @ Wx^T (both dirs, split-K=4 atomic): grid(x=dir, y=Mtiles, z=splitK)
    gemm_tf32<96,0,1><<<dim3(2,16,4), 192, SMEM96>>>(
        p_xc, CED, (size_t)BLED, Wx, Wx_b, CED, p_dbc, 96, (size_t)CML*96, CED, nullptr, nullptr);

    // 4) delta = softplus(dbc[:, :64] @ Wdt^T + b_dt)  (both dirs, z=dir)
    gemm_tf32<128,1,2><<<dim3(16,16,2), 256, SMEM128>>>(
        p_dbc, 96, (size_t)CML*96, Wdt, Wdt_b, CRK, p_delta, CED, (size_t)BLED, CRK, b_dt, b_dt_b);

    // 5) selective scan + gating, both dirs
    scan_kernel<<<dim3(CED/128, CB, 2), 128>>>(
        p_delta, p_xc, p_dbc, p_xz, A_log, A_log_b, Dp, Dp_b, p_y);

    // 6) combine
    combine_kernel<<<BLED/256, 256>>>(p_y, p_y + BLED, p_yc);

    // 7) out = yc @ W_out^T : [2048,2048] x [1024,2048]^T
    gemm_tf32<64,0,0><<<dim3(16,16,1), 128, SMEM64>>>(
        p_yc, CED, 0, W_out, W_out, CED, out, CD, 0, CED, nullptr, nullptr);
}

// round 5
// speedup vs baseline: 1.3345x; 1.3345x over previous
#include <cuda_runtime.h>
#include <cuda_fp16.h>
#include <cstdint>

// ---------------- Problem constants ----------------
#define CB   4
#define CL   512
#define CD   1024
#define CED  2048
#define CNS  16
#define CRK  64
#define CKC  4
#define CML  (CB*CL)        // 2048
#define BLED (CB*CL*CED)    // 4194304

// ---------------- Scratch ----------------
__device__ float  g_xz[CB*CL*2*CED];     // xz fp32 (x half | z half)
__device__ __half g_xch[2*BLED];         // conv+silu output (half)
__device__ float  g_dbc[2*CML*96];       // split-K accumulators (fp32)
__device__ __half g_dbch[2*CML*96];      // dbc as half (for delta GEMM)
__device__ float  g_delta[2*BLED];       // softplus(delta) fp32
__device__ float  g_y[2*BLED];           // scan output fp32
__device__ __half g_ych[BLED];           // combined (half)
__device__ __half g_xh[CML*CD];          // x as half
__device__ __half g_wh[7077888];         // W_in | W_out | Wx f | Wx b | Wdt f | Wdt b
#define OW_IN   0
#define OW_OUT  4194304
#define OWX_F   6291456
#define OWX_B   6488064
#define OWDT_F  6684672
#define OWDT_B  6815744
// total = 6946816 <= 7077888

// ---------------- helpers ----------------
__device__ __forceinline__ float softplusf(float x) {
    return fmaxf(x, 0.f) + log1pf(__expf(-fabsf(x)));
}
__device__ __forceinline__ float siluf(float x) {
    return x / (1.f + __expf(-x));
}
__device__ __forceinline__ float ex2f(float x) {
    float y; asm("ex2.approx.ftz.f32 %0, %1;" : "=f"(y) : "f"(x));
    return y;
}
__device__ __forceinline__ void cp16(uint32_t dst, const void* src) {
    asm volatile("cp.async.cg.shared.global [%0], [%1], 16;" :: "r"(dst), "l"(src));
}
__device__ __forceinline__ void ldsm4(uint32_t& r0, uint32_t& r1, uint32_t& r2, uint32_t& r3, uint32_t addr) {
    asm volatile("ldmatrix.sync.aligned.m8n8.x4.shared.b16 {%0,%1,%2,%3}, [%4];"
                 : "=r"(r0), "=r"(r1), "=r"(r2), "=r"(r3) : "r"(addr));
}

// ---------------- elementwise convert / zero ----------------
__global__ void f2h_k(const float2* __restrict__ in, __half2* __restrict__ out, int n2) {
    int i = blockIdx.x * blockDim.x + threadIdx.x;
    if (i < n2) {
        float2 v = in[i];
        out[i] = __floats2half2_rn(v.x, v.y);
    }
}
__global__ void zero_k(float4* __restrict__ p, int n4) {
    int i = blockIdx.x * blockDim.x + threadIdx.x;
    if (i < n4) p[i] = make_float4(0.f, 0.f, 0.f, 0.f);
}

// ================= FP16 tensor-core NT GEMM =================
// C[M,N] = A[M,K] * B[N,K]^T, fp32 accumulate. BM=128, BK=64 halfs, 2-stage cp.async.
// Warp tile 64x32 (mma m16n8k16). Smem row stride 72 halfs (144B) -> bank-clean.
// EPI: 0 none, 1 softplus(acc + bias[n]).
// DIRAX: 0 none; 1 dir=blockIdx.x (col0=0), split-K on z (atomic); 2 dir=blockIdx.z.
#define LDKH 72
template<int BN, int EPI, int DIRAX>
__global__ void __launch_bounds__(2*(BN/32)*32)
gemm_f16(const __half* __restrict__ A, int lda, size_t aStride,
         const __half* __restrict__ B0, const __half* __restrict__ B1, int ldb,
         float* __restrict__ C, int ldc, size_t cStride,
         int K, const float* __restrict__ bias0, const float* __restrict__ bias1)
{
    constexpr int BM = 128;
    constexpr int WARPS_N = BN/32;
    constexpr int THREADS = 2*WARPS_N*32;
    constexpr int STAGE_H = (BM+BN)*LDKH;       // halfs per stage
    extern __shared__ __half smh[];

    const int tid  = threadIdx.x;
    const int warp = tid >> 5, lane = tid & 31;
    const int wm = warp / WARPS_N, wn = warp % WARPS_N;
    const int g = lane >> 2, t = lane & 3;

    const int dir = (DIRAX==1) ? blockIdx.x : (DIRAX==2 ? blockIdx.z : 0);
    const int row0 = blockIdx.y * BM;
    const int col0 = (DIRAX==1) ? 0 : blockIdx.x * BN;
    const int nsplit = (DIRAX==1) ? gridDim.z : 1;
    const int Kc = K / nsplit;
    const int kbase = (DIRAX==1) ? blockIdx.z * Kc : 0;
    const int KT = Kc / 64;

    const __half* Aeff = A + (size_t)dir * aStride;
    const __half* Beff = dir ? B1 : B0;
    float*        Ceff = C + (size_t)dir * cStride;
    const float*  bias = dir ? bias1 : bias0;

    float acc[4][4][4];
#pragma unroll
    for (int i = 0; i < 4; i++)
#pragma unroll
        for (int j = 0; j < 4; j++)
#pragma unroll
            for (int q = 0; q < 4; q++) acc[i][j][q] = 0.f;

    const uint32_t smem0 = (uint32_t)__cvta_generic_to_shared(smh);

    // ldmatrix.x4 A lane offset (bytes within stage): 16x16 tile per (mt, ks)
    const uint32_t aLane = (uint32_t)(((wm*64 + (lane & 7) + ((lane >> 3) & 1) * 8) * LDKH
                                     + (lane >> 4) * 8) * 2);
    // B fragment scalar LDS base (bytes within stage, B region starts at BM*LDKH halfs)
    const uint32_t bLane = (uint32_t)((BM*LDKH + (wn*32 + g) * LDKH + 2*t) * 2);

    auto load_tile = [&](int kt, int s) {
        __half* As = smh + s*STAGE_H;
        __half* Bs = As + BM*LDKH;
        const int k0 = kbase + kt*64;
#pragma unroll 2
        for (int i = tid; i < BM*8; i += THREADS) {
            int m = i >> 3, kq = (i & 7) << 3;    // 8-half (16B) chunks
            cp16((uint32_t)__cvta_generic_to_shared(As + m*LDKH + kq),
                 Aeff + (size_t)(row0+m)*lda + k0 + kq);
        }
#pragma unroll 2
        for (int i = tid; i < BN*8; i += THREADS) {
            int n = i >> 3, kq = (i & 7) << 3;
            cp16((uint32_t)__cvta_generic_to_shared(Bs + n*LDKH + kq),
                 Beff + (size_t)(col0+n)*ldb + k0 + kq);
        }
        asm volatile("cp.async.commit_group;");
    };

    auto comp = [&](int s) {
        const uint32_t base = smem0 + (uint32_t)(s*STAGE_H)*2u;
#pragma unroll
        for (int ks = 0; ks < 4; ks++) {          // 4 k-steps of 16
            const uint32_t kb = (uint32_t)(ks*16)*2u;
            uint32_t a[4][4];
#pragma unroll
            for (int mt = 0; mt < 4; mt++)
                ldsm4(a[mt][0], a[mt][1], a[mt][2], a[mt][3],
                      base + aLane + (uint32_t)(mt*16*LDKH)*2u + kb);
#pragma unroll
            for (int nt = 0; nt < 4; nt++) {
                uint32_t b0, b1;
                const uint32_t baddr = base + bLane + (uint32_t)(nt*8*LDKH)*2u + kb;
                asm volatile("ld.shared.b32 %0, [%1];" : "=r"(b0) : "r"(baddr));
                asm volatile("ld.shared.b32 %0, [%1];" : "=r"(b1) : "r"(baddr + 16u));
#pragma unroll
                for (int mt = 0; mt < 4; mt++)
                    asm volatile(
                        "mma.sync.aligned.m16n8k16.row.col.f32.f16.f16.f32 "
                        "{%0,%1,%2,%3}, {%4,%5,%6,%7}, {%8,%9}, {%0,%1,%2,%3};"
                        : "+f"(acc[mt][nt][0]), "+f"(acc[mt][nt][1]),
                          "+f"(acc[mt][nt][2]), "+f"(acc[mt][nt][3])
                        : "r"(a[mt][0]), "r"(a[mt][1]), "r"(a[mt][2]), "r"(a[mt][3]),
                          "r"(b0), "r"(b1));
            }
        }
    };

    load_tile(0, 0);
    for (int kt = 0; kt < KT; kt++) {
        if (kt + 1 < KT) {
            load_tile(kt + 1, (kt + 1) & 1);
            asm volatile("cp.async.wait_group 1;");
        } else {
            asm volatile("cp.async.wait_group 0;");
        }
        __syncthreads();
        comp(kt & 1);
        __syncthreads();
    }

    const bool use_atomic = (DIRAX == 1 && nsplit > 1);
#pragma unroll
    for (int mt = 0; mt < 4; mt++) {
        int row = row0 + wm*64 + mt*16 + g;
#pragma unroll
        for (int nt = 0; nt < 4; nt++) {
            int col = col0 + wn*32 + nt*8 + 2*t;
            float v0 = acc[mt][nt][0], v1 = acc[mt][nt][1];
            float v2 = acc[mt][nt][2], v3 = acc[mt][nt][3];
            if (EPI == 1) {
                v0 = softplusf(v0 + bias[col]);
                v1 = softplusf(v1 + bias[col+1]);
                v2 = softplusf(v2 + bias[col]);
                v3 = softplusf(v3 + bias[col+1]);
            }
            if (use_atomic) {
                atomicAdd(&Ceff[(size_t)row*ldc + col],       v0);
                atomicAdd(&Ceff[(size_t)row*ldc + col + 1],   v1);
                atomicAdd(&Ceff[(size_t)(row+8)*ldc + col],   v2);
                atomicAdd(&Ceff[(size_t)(row+8)*ldc + col+1], v3);
            } else {
                *(float2*)&Ceff[(size_t)row*ldc + col]     = make_float2(v0, v1);
                *(float2*)&Ceff[(size_t)(row+8)*ldc + col] = make_float2(v2, v3);
            }
        }
    }
}

// ---------------- causal depthwise conv + SiLU (both dirs) -> half ----------
__global__ void conv_silu_kernel(const float* __restrict__ xz,
                                 const float* __restrict__ cw0, const float* __restrict__ cb0,
                                 const float* __restrict__ cw1, const float* __restrict__ cb1,
                                 __half* __restrict__ xch)
{
    int idx = blockIdx.x * blockDim.x + threadIdx.x;
    int e   = idx & (CED-1);
    int t   = (idx >> 11) & (CL-1);
    int b   = (idx >> 20) & (CB-1);
    int dir = idx >> 22;

    const float* w = dir ? cw1 : cw0;
    float acc = (dir ? cb1 : cb0)[e];
#pragma unroll
    for (int j = 0; j < CKC; j++) {
        int ts = t - (CKC-1) + j;
        if (ts >= 0) {
            int tg = dir ? (CL-1-ts) : ts;
            acc = fmaf(w[e*CKC + j], xz[((size_t)(b*CL + tg) << 12) + e], acc);
        }
    }
    xch[idx] = __float2half_rn(siluf(acc));
}

// ---------------- selective scan, both dirs in one launch -----------------
#define SCAN_TC 16
__global__ void __launch_bounds__(128)
scan_kernel(const float* __restrict__ delta,
            const __half* __restrict__ xc,
            const float* __restrict__ dbc,
            const float* __restrict__ xz,
            const float* __restrict__ A_log_f, const float* __restrict__ A_log_b,
            const float* __restrict__ Dp_f,    const float* __restrict__ Dp_b,
            float* __restrict__ y)
{
    __shared__ float sD[SCAN_TC][128];
    __shared__ float sX[SCAN_TC][128];
    __shared__ float sZ[SCAN_TC][128];
    __shared__ float sB[SCAN_TC][CNS];
    __shared__ float sC[SCAN_TC][CNS];

    const int e   = blockIdx.x * 128 + threadIdx.x;
    const int b   = blockIdx.y;
    const int dir = blockIdx.z;
    const int tx  = threadIdx.x;

    const float*  dlt = delta + (size_t)dir * BLED;
    const __half* xcd = xc    + (size_t)dir * BLED;
    const float*  dbd = dbc   + (size_t)dir * CML * 96;
    float*        yd  = y     + (size_t)dir * BLED;
    const float* A_log = dir ? A_log_b : A_log_f;
    const float* Dp    = dir ? Dp_b    : Dp_f;

    float Areg[CNS];
#pragma unroll
    for (int n = 0; n < CNS; n++)
        Areg[n] = -__expf(A_log[e*CNS + n]) * 1.4426950408889634f;
    const float Dpe = Dp[e];

    float h[CNS];
#pragma unroll
    for (int n = 0; n < CNS; n++) h[n] = 0.f;

    for (int t0 = 0; t0 < CL; t0 += SCAN_TC) {
        __syncthreads();
#pragma unroll
        for (int it = 0; it < SCAN_TC; it++) {
            int t = t0 + it;
            size_t r = (size_t)(b*CL + t) * CED + e;
            sD[it][tx] = dlt[r];
            sX[it][tx] = __half2float(xcd[r]);
            int tz = dir ? (CL-1-t) : t;
            sZ[it][tx] = xz[((size_t)(b*CL + tz) << 12) + CED + e];
        }
        for (int j = tx; j < SCAN_TC*CNS; j += 128) {
            int it = j >> 4, n = j & (CNS-1);
            size_t r = (size_t)(b*CL + t0 + it) * 96;
            sB[it][n] = dbd[r + CRK + n];
            sC[it][n] = dbd[r + CRK + CNS + n];
        }
        __syncthreads();

#pragma unroll
        for (int it = 0; it < SCAN_TC; it++) {
            float d  = sD[it][tx];
            float xv = sX[it][tx];
            float dx = d * xv;
            float y0 = 0.f, y1 = 0.f, y2 = 0.f, y3 = 0.f;
#pragma unroll
            for (int n = 0; n < CNS; n += 4) {
                float dA0 = ex2f(d * Areg[n+0]);
                float dA1 = ex2f(d * Areg[n+1]);
                float dA2 = ex2f(d * Areg[n+2]);
                float dA3 = ex2f(d * Areg[n+3]);
                h[n+0] = fmaf(dA0, h[n+0], dx * sB[it][n+0]);
                h[n+1] = fmaf(dA1, h[n+1], dx * sB[it][n+1]);
                h[n+2] = fmaf(dA2, h[n+2], dx * sB[it][n+2]);
                h[n+3] = fmaf(dA3, h[n+3], dx * sB[it][n+3]);
                y0 = fmaf(h[n+0], sC[it][n+0], y0);
                y1 = fmaf(h[n+1], sC[it][n+1], y1);
                y2 = fmaf(h[n+2], sC[it][n+2], y2);
                y3 = fmaf(h[n+3], sC[it][n+3], y3);
            }
            float zv = sZ[it][tx];
            float yo = ((y0+y1) + (y2+y3)) + Dpe * xv;
            yd[(size_t)(b*CL + t0 + it)*CED + e] = yo * siluf(zv);
        }
    }
}

// ---------------- combine -> half ------------------
__global__ void combine_kernel(const float* __restrict__ y0,
                               const float* __restrict__ y1,
                               __half* __restrict__ yc)
{
    int idx = blockIdx.x * blockDim.x + threadIdx.x;
    int e = idx & (CED-1);
    int t = (idx >> 11) & (CL-1);
    int b = idx >> 20;
    float a  = y0[idx];
    float bb = y1[(size_t)(b*CL + (CL-1-t))*CED + e];
    yc[idx] = __float2half_rn(0.5f * (a + bb));
}

// ---------------- launch ----------------
extern "C" void kernel_launch(void* const* d_in, const int* in_sizes, int n_in,
                              void* d_out, int out_size)
{
    const float* x      = (const float*)d_in[0];
    const float* W_in   = (const float*)d_in[1];
    const float* conv_w = (const float*)d_in[2];
    const float* conv_b = (const float*)d_in[3];
    const float* Wx     = (const float*)d_in[4];
    const float* Wdt    = (const float*)d_in[5];
    const float* b_dt   = (const float*)d_in[6];
    const float* A_log  = (const float*)d_in[7];
    const float* Dp     = (const float*)d_in[8];
    const float* conv_w_b = (const float*)d_in[9];
    const float* conv_b_b = (const float*)d_in[10];
    const float* Wx_b   = (const float*)d_in[11];
    const float* Wdt_b  = (const float*)d_in[12];
    const float* b_dt_b = (const float*)d_in[13];
    const float* A_log_b= (const float*)d_in[14];
    const float* Dp_b   = (const float*)d_in[15];
    const float* W_out  = (const float*)d_in[16];
    float* out = (float*)d_out;

    float *p_xz, *p_dbc, *p_delta, *p_y;
    __half *p_xch, *p_dbch, *p_ych, *p_xh, *p_wh;
    cudaGetSymbolAddress((void**)&p_xz,    g_xz);
    cudaGetSymbolAddress((void**)&p_xch,   g_xch);
    cudaGetSymbolAddress((void**)&p_dbc,   g_dbc);
    cudaGetSymbolAddress((void**)&p_dbch,  g_dbch);
    cudaGetSymbolAddress((void**)&p_delta, g_delta);
    cudaGetSymbolAddress((void**)&p_y,     g_y);
    cudaGetSymbolAddress((void**)&p_ych,   g_ych);
    cudaGetSymbolAddress((void**)&p_xh,    g_xh);
    cudaGetSymbolAddress((void**)&p_wh,    g_wh);

    constexpr int SMEM128 = 2*(128+128)*LDKH*2;   // 73728
    constexpr int SMEM96  = 2*(128+96) *LDKH*2;   // 64512
    cudaFuncSetAttribute(gemm_f16<128,0,0>, cudaFuncAttributeMaxDynamicSharedMemorySize, SMEM128);
    cudaFuncSetAttribute(gemm_f16<128,1,2>, cudaFuncAttributeMaxDynamicSharedMemorySize, SMEM128);
    cudaFuncSetAttribute(gemm_f16<96,0,1>,  cudaFuncAttributeMaxDynamicSharedMemorySize, SMEM96);

    // 0) zero dbc accumulators; convert operands to half
    zero_k<<<(2*CML*96/4 + 255)/256, 256>>>((float4*)p_dbc, 2*CML*96/4);
    f2h_k<<<(CML*CD/2 + 255)/256, 256>>>((const float2*)x, (__half2*)p_xh, CML*CD/2);
    f2h_k<<<(4194304/2 + 255)/256, 256>>>((const float2*)W_in,  (__half2*)(p_wh+OW_IN),  4194304/2);
    f2h_k<<<(2097152/2 + 255)/256, 256>>>((const float2*)W_out, (__half2*)(p_wh+OW_OUT), 2097152/2);
    f2h_k<<<(196608/2  + 255)/256, 256>>>((const float2*)Wx,    (__half2*)(p_wh+OWX_F),  196608/2);
    f2h_k<<<(196608/2  + 255)/256, 256>>>((const float2*)Wx_b,  (__half2*)(p_wh+OWX_B),  196608/2);
    f2h_k<<<(131072/2  + 255)/256, 256>>>((const float2*)Wdt,   (__half2*)(p_wh+OWDT_F), 131072/2);
    f2h_k<<<(131072/2  + 255)/256, 256>>>((const float2*)Wdt_b, (__half2*)(p_wh+OWDT_B), 131072/2);

    // 1) xz = x @ W_in^T : [2048,1024] x [4096,1024]^T  (fp16 TC)
    gemm_f16<128,0,0><<<dim3(32,16,1), 256, SMEM128>>>(
        p_xh, CD, 0, p_wh+OW_IN, p_wh+OW_IN, CD, p_xz, 2*CED, 0, CD, nullptr, nullptr);

    // 2) conv + silu (both dirs) -> half
    conv_silu_kernel<<<(2*BLED)/256, 256>>>(p_xz, conv_w, conv_b, conv_w_b, conv_b_b, p_xch);

    // 3) dbc = xc @ Wx^T (both dirs, split-K=4 atomic): grid(x=dir, y=Mtiles, z=splitK)
    gemm_f16<96,0,1><<<dim3(2,16,4), 192, SMEM96>>>(
        p_xch, CED, (size_t)BLED, p_wh+OWX_F, p_wh+OWX_B, CED,
        p_dbc, 96, (size_t)CML*96, CED, nullptr, nullptr);

    // 3b) dbc -> half (for delta GEMM)
    f2h_k<<<(2*CML*96/2 + 255)/256, 256>>>((const float2*)p_dbc, (__half2*)p_dbch, 2*CML*96/2);

    // 4) delta = softplus(dbc[:, :64] @ Wdt^T + b_dt)  (both dirs, z=dir)
    gemm_f16<128,1,2><<<dim3(16,16,2), 256, SMEM128>>>(
        p_dbch, 96, (size_t)CML*96, p_wh+OWDT_F, p_wh+OWDT_B, CRK,
        p_delta, CED, (size_t)BLED, CRK, b_dt, b_dt_b);

    // 5) selective scan + gating, both dirs
    scan_kernel<<<dim3(CED/128, CB, 2), 128>>>(
        p_delta, p_xch, p_dbc, p_xz, A_log, A_log_b, Dp, Dp_b, p_y);

    // 6) combine -> half
    combine_kernel<<<BLED/256, 256>>>(p_y, p_y + BLED, p_ych);

    // 7) out = yc @ W_out^T : [2048,2048] x [1024,2048]^T  (fp16 TC)
    gemm_f16<128,0,0><<<dim3(8,16,1), 256, SMEM128>>>(
        p_ych, CED, 0, p_wh+OW_OUT, p_wh+OW_OUT, CED, out, CD, 0, CED, nullptr, nullptr);
}